// round 16
// baseline (speedup 1.0000x reference)
#include <cuda_runtime.h>

// Masked inclusive cumsum along rows — single-pass decoupled lookback.
//   x:    [2048, 32768] fp32
//   mask: [2048, 32768] bool serialized as INT32 (0/1)
//   out[r,j] = sum_{i<=j} (mask[r,i] ? x[r,i] : 0)
//
// R15: one CTA per TILE (2048 rows x 8 tiles = 16384 CTAs), 1024 threads,
// 4096 elements/tile (float4+int4 per thread). Cross-tile prefix via
// decoupled lookback: per-tile 64-bit descriptor {value,flag} written with
// a single atomic 64-bit volatile store (flag 1 = aggregate, 2 = inclusive
// prefix). Tile 0 of each row publishes flag 2 directly, so lookback walks
// <= 7 predecessors. Loads are first in every CTA -> full MLP from the
// block scheduler instead of 2 serial tile-chains per SM.

#define NCOLS     32768
#define THREADS   1024
#define TILE      (THREADS * 4)            // 4096
#define TPR       (NCOLS / TILE)           // 8 tiles per row
#define NTILES_T  (2048 * TPR)             // 16384 total tiles

__device__ unsigned long long g_desc[NTILES_T];

__device__ __forceinline__ unsigned long long pack_desc(float v, unsigned f) {
    return ((unsigned long long)__float_as_uint(v) << 32) | (unsigned long long)f;
}

__global__ void init_desc_kernel()
{
    int i = blockIdx.x * blockDim.x + threadIdx.x;
    if (i < NTILES_T) g_desc[i] = 0ULL;
}

__global__ void __launch_bounds__(THREADS, 2)
masked_cumsum_lookback(const float4* __restrict__ x,
                       const int4*   __restrict__ mask,
                       float4*       __restrict__ out)
{
    __shared__ float warp_sums[32];
    __shared__ float s_excl;

    const int bid  = blockIdx.x;
    const int tile = bid & (TPR - 1);      // tile index within row
    const int tid  = threadIdx.x;
    const int lane = tid & 31;
    const int wid  = tid >> 5;

    // Global float4 index of this thread's element.
    const size_t g = (size_t)bid * THREADS + tid;

    // 1. Loads first — nothing in front of them.
    float4 v = x[g];
    int4   m = mask[g];

    // 2. Masked thread-local inclusive prefix (4 elements).
    float a0 = m.x ? v.x : 0.0f;
    float a1 = m.y ? v.y : 0.0f;
    float a2 = m.z ? v.z : 0.0f;
    float a3 = m.w ? v.w : 0.0f;
    float s1 = a0;
    float s2 = s1 + a1;
    float s3 = s2 + a2;
    float s4 = s3 + a3;

    // 3. Warp inclusive scan of per-thread sums.
    float incl = s4;
    #pragma unroll
    for (int d = 1; d < 32; d <<= 1) {
        float n = __shfl_up_sync(0xffffffffu, incl, d);
        if (lane >= d) incl += n;
    }
    if (lane == 31) warp_sums[wid] = incl;
    __syncthreads();

    // 4. Warp 0: scan warp totals, publish aggregate, lookback.
    if (wid == 0) {
        float ws = warp_sums[lane];
        #pragma unroll
        for (int d = 1; d < 32; d <<= 1) {
            float n = __shfl_up_sync(0xffffffffu, ws, d);
            if (lane >= d) ws += n;
        }
        warp_sums[lane] = ws;
        const float block_agg = __shfl_sync(0xffffffffu, ws, 31);

        if (lane == 0) {
            float excl = 0.0f;
            if (tile == 0) {
                // Row head: aggregate IS the inclusive prefix.
                *(volatile unsigned long long*)&g_desc[bid] =
                    pack_desc(block_agg, 2u);
            } else {
                *(volatile unsigned long long*)&g_desc[bid] =
                    pack_desc(block_agg, 1u);
                // Serial lookback, depth <= 7 (tile 0 always has flag 2).
                int p = bid - 1;
                for (;;) {
                    unsigned long long d;
                    do {
                        d = *(volatile unsigned long long*)&g_desc[p];
                    } while ((unsigned)d == 0u);
                    excl += __uint_as_float((unsigned)(d >> 32));
                    if (((unsigned)d) == 2u) break;
                    --p;
                }
                *(volatile unsigned long long*)&g_desc[bid] =
                    pack_desc(excl + block_agg, 2u);
            }
            s_excl = excl;
        }
    }
    __syncthreads();

    // 5. Compose and store.
    const float warp_off = (wid > 0) ? warp_sums[wid - 1] : 0.0f;
    const float base = s_excl + warp_off + (incl - s4);

    float4 o;
    o.x = base + s1;
    o.y = base + s2;
    o.z = base + s3;
    o.w = base + s4;
    out[g] = o;
}

extern "C" void kernel_launch(void* const* d_in, const int* in_sizes, int n_in,
                              void* d_out, int out_size)
{
    const float4* x    = (const float4*)d_in[0];
    const int4*   mask = (const int4*)d_in[1];
    float4*       out  = (float4*)d_out;

    init_desc_kernel<<<(NTILES_T + 1023) / 1024, 1024>>>();

    const int rows = in_sizes[0] / NCOLS;          // 2048
    masked_cumsum_lookback<<<rows * TPR, THREADS>>>(x, mask, out);
}